// round 15
// baseline (speedup 1.0000x reference)
#include <cuda_runtime.h>
#include <cuda_fp16.h>
#include <math.h>

#define Nn 50000
#define Ee 800000
#define ETOT 850000
#define Hh 96
#define Gg 64
#define NCLS 4
#define BNEPS 1e-5f

// ---------------- device scratch ----------------
__device__ float g_h[Nn * Hh];
__device__ float g_id[Nn * Hh];
__device__ __half g_hph[Nn * Hh];    // hp in fp16
__device__ float g_tmp[Nn * Hh];
__device__ float g_ss[Nn], g_sd[Nn];
__device__ int   g_deg[Nn];
__device__ int   g_rs[Nn + 1];
__device__ int   g_cur[Nn];
__device__ int   g_csr[ETOT];
__device__ float g_bnsum[3 * Hh], g_bnsq[3 * Hh];
__device__ float g_pooled[Gg * Hh];
__device__ float g_cnt[Gg];

__device__ __forceinline__ float lrelu01(float v) { return v >= 0.f ? v : 0.01f * v; }

// ---------------- zero / init ----------------
__global__ void zero_k() {
    int i = blockIdx.x * blockDim.x + threadIdx.x;
    int stride = gridDim.x * blockDim.x;
    for (int j = i; j < Nn; j += stride) g_deg[j] = 0;
    if (i < Gg * Hh) g_pooled[i] = 0.f;
    if (i < Gg) g_cnt[i] = 0.f;
    if (i < 3 * Hh) { g_bnsum[i] = 0.f; g_bnsq[i] = 0.f; }
}

// ---------------- CSR build ----------------
__global__ void count_k(const int* __restrict__ ei) {
    int i = blockIdx.x * blockDim.x + threadIdx.x;
    if (i >= ETOT) return;
    int d = (i < Ee) ? ei[Ee + i] : (i - Ee);
    atomicAdd(&g_deg[d], 1);
}

__global__ void scan_k() {
    __shared__ int part[1024];
    int t = threadIdx.x;
    const int CH = (Nn + 1023) / 1024;
    int base = t * CH;
    int s = 0;
    for (int i = 0; i < CH; i++) {
        int idx = base + i;
        if (idx < Nn) s += g_deg[idx];
    }
    part[t] = s;
    __syncthreads();
    for (int off = 1; off < 1024; off <<= 1) {
        int v = (t >= off) ? part[t - off] : 0;
        __syncthreads();
        part[t] += v;
        __syncthreads();
    }
    int run = (t == 0) ? 0 : part[t - 1];
    for (int i = 0; i < CH; i++) {
        int idx = base + i;
        if (idx < Nn) {
            g_rs[idx] = run;
            g_cur[idx] = run;
            run += g_deg[idx];
        }
    }
    if (t == blockDim.x - 1) g_rs[Nn] = part[blockDim.x - 1];
}

__global__ void scatter_k(const int* __restrict__ ei) {
    int i = blockIdx.x * blockDim.x + threadIdx.x;
    if (i >= ETOT) return;
    int sN, dN;
    if (i < Ee) { sN = ei[i]; dN = ei[Ee + i]; }
    else        { sN = i - Ee; dN = i - Ee; }
    int pos = atomicAdd(&g_cur[dN], 1);
    g_csr[pos] = sN;
}

// ---------------- embed GEMM (K=256): proven gemm128 core ----------------
__global__ __launch_bounds__(384, 2) void gemm128_emb(
    const float* __restrict__ A, const float* __restrict__ W,
    const float* __restrict__ bias,
    float* __restrict__ C, float* __restrict__ C2, int M, int K)
{
    __shared__ __align__(16) float Ash[32][132];
    __shared__ float Wsh[32][96];
    int tid = threadIdx.x;
    int cg = tid % 24;
    int rg = tid / 24;
    int rowBase = blockIdx.x * 128;
    float acc[8][4] = {};
    for (int kc = 0; kc < K; kc += 32) {
        for (int idx = tid; idx < 1024; idx += 384) {
            int m = idx >> 3, kq = idx & 7;
            int r = rowBase + m;
            float4 v = make_float4(0.f, 0.f, 0.f, 0.f);
            if (r < M) v = *(const float4*)&A[r * K + kc + kq * 4];
            int k0 = kq * 4;
            Ash[k0 + 0][m] = v.x;
            Ash[k0 + 1][m] = v.y;
            Ash[k0 + 2][m] = v.z;
            Ash[k0 + 3][m] = v.w;
        }
        #pragma unroll
        for (int j = 0; j < 8; j++) {
            int idx = tid + j * 384;
            int k = idx / 96, c = idx % 96;
            Wsh[k][c] = W[(kc + k) * 96 + c];
        }
        __syncthreads();
        #pragma unroll
        for (int k = 0; k < 32; k++) {
            float4 al = *(const float4*)&Ash[k][rg * 8];
            float4 ah = *(const float4*)&Ash[k][rg * 8 + 4];
            float4 w  = *(const float4*)&Wsh[k][cg * 4];
            float av[8] = {al.x, al.y, al.z, al.w, ah.x, ah.y, ah.z, ah.w};
            float wv[4] = {w.x, w.y, w.z, w.w};
            #pragma unroll
            for (int i = 0; i < 8; i++)
                #pragma unroll
                for (int j = 0; j < 4; j++)
                    acc[i][j] = fmaf(av[i], wv[j], acc[i][j]);
        }
        __syncthreads();
    }
    int c0 = cg * 4;
    float bv[4];
    #pragma unroll
    for (int j = 0; j < 4; j++) bv[j] = bias[c0 + j];
    int r0 = rowBase + rg * 8;
    #pragma unroll
    for (int i = 0; i < 8; i++) {
        int r = r0 + i;
        if (r < M) {
            float v0 = lrelu01(acc[i][0] + bv[0]);
            float v1 = lrelu01(acc[i][1] + bv[1]);
            float v2 = lrelu01(acc[i][2] + bv[2]);
            float v3 = lrelu01(acc[i][3] + bv[3]);
            float4 o = make_float4(v0, v1, v2, v3);
            *(float4*)&C[r * 96 + c0] = o;
            *(float4*)&C2[r * 96 + c0] = o;
        }
    }
}

// ---------------- K=96 GEMM: W resident + double-buffered A ----------------
#define DSM96 (96 * 96 * 4 + 2 * 32 * 132 * 4)   // 70656
template <int ACT, int MODE, int SCORES>
__global__ __launch_bounds__(384, 2) void gemm96w(
    const float* __restrict__ A, const float* __restrict__ A2,
    const float* __restrict__ gma, const float* __restrict__ bta,
    const float* __restrict__ sumP, const float* __restrict__ sqP,
    const float* __restrict__ W, const float* __restrict__ bias,
    const float* __restrict__ as_, const float* __restrict__ ad_,
    float* __restrict__ ssO, float* __restrict__ sdO,
    void* __restrict__ Cv, int M)
{
    extern __shared__ __align__(16) float dsm[];
    float* Wsh = dsm;                                  // [96*96]
    float (*Ash)[32][132] = (float (*)[32][132])(dsm + 9216);   // [2][32][132]
    float2 (*sSD)[25] = (float2 (*)[25])(dsm + 9216);  // reuses Ash region
    __shared__ float s_sc[96], s_sh[96];
    int tid = threadIdx.x;
    #pragma unroll
    for (int j = 0; j < 24; j++) Wsh[tid + j * 384] = W[tid + j * 384];
    if (MODE == 1) {
        if (tid < 96) {
            float mu = sumP[tid] * (1.f / Nn);
            float var = sqP[tid] * (1.f / Nn) - mu * mu;
            float is = rsqrtf(var + BNEPS);
            float gv = gma[tid];
            s_sc[tid] = gv * is;
            s_sh[tid] = bta[tid] - mu * gv * is;
        }
        __syncthreads();
    }
    int cg = tid % 24;
    int rg = tid / 24;
    int rowBase = blockIdx.x * 128;
    float acc[8][4] = {};
    float4 pf[3];

    auto loadA = [&](int kc) {
        #pragma unroll
        for (int it = 0; it < 3; it++) {
            int idx = tid + it * 384;
            if (idx < 1024) {
                int m = idx >> 3, kq = idx & 7;
                int r = rowBase + m;
                float4 v = make_float4(0.f, 0.f, 0.f, 0.f);
                if (r < M) {
                    v = *(const float4*)&A[r * 96 + kc + kq * 4];
                    if (MODE == 1) {
                        float4 u = *(const float4*)&A2[r * 96 + kc + kq * 4];
                        int c = kc + kq * 4;
                        v.x = lrelu01(fmaf(v.x, s_sc[c + 0], s_sh[c + 0])) + u.x;
                        v.y = lrelu01(fmaf(v.y, s_sc[c + 1], s_sh[c + 1])) + u.y;
                        v.z = lrelu01(fmaf(v.z, s_sc[c + 2], s_sh[c + 2])) + u.z;
                        v.w = lrelu01(fmaf(v.w, s_sc[c + 3], s_sh[c + 3])) + u.w;
                    }
                }
                pf[it] = v;
            }
        }
    };
    auto stsA = [&](int buf) {
        #pragma unroll
        for (int it = 0; it < 3; it++) {
            int idx = tid + it * 384;
            if (idx < 1024) {
                int m = idx >> 3, kq = idx & 7;
                int k0 = kq * 4;
                Ash[buf][k0 + 0][m] = pf[it].x;
                Ash[buf][k0 + 1][m] = pf[it].y;
                Ash[buf][k0 + 2][m] = pf[it].z;
                Ash[buf][k0 + 3][m] = pf[it].w;
            }
        }
    };

    loadA(0);
    stsA(0);
    __syncthreads();
    #pragma unroll
    for (int c = 0; c < 3; c++) {
        if (c < 2) loadA((c + 1) * 32);
        int buf = c & 1;
        const float* wrow = Wsh + c * 32 * 96 + cg * 4;
        #pragma unroll
        for (int k = 0; k < 32; k++) {
            float4 al = *(const float4*)&Ash[buf][k][rg * 8];
            float4 ah = *(const float4*)&Ash[buf][k][rg * 8 + 4];
            float4 w  = *(const float4*)(wrow + k * 96);
            float av[8] = {al.x, al.y, al.z, al.w, ah.x, ah.y, ah.z, ah.w};
            float wv[4] = {w.x, w.y, w.z, w.w};
            #pragma unroll
            for (int i = 0; i < 8; i++)
                #pragma unroll
                for (int j = 0; j < 4; j++)
                    acc[i][j] = fmaf(av[i], wv[j], acc[i][j]);
        }
        if (c < 2) {
            stsA(buf ^ 1);
            __syncthreads();
        }
    }
    __syncthreads();   // Ash dead; safe to alias as sSD

    int c0 = cg * 4;
    float bv[4];
    #pragma unroll
    for (int j = 0; j < 4; j++) bv[j] = bias ? bias[c0 + j] : 0.f;
    float asv[4], adv[4];
    if (SCORES) {
        #pragma unroll
        for (int j = 0; j < 4; j++) { asv[j] = as_[c0 + j]; adv[j] = ad_[c0 + j]; }
    }
    int r0 = rowBase + rg * 8;
    #pragma unroll
    for (int i = 0; i < 8; i++) {
        int r = r0 + i;
        if (SCORES) {
            float s1 = acc[i][0] * asv[0] + acc[i][1] * asv[1] + acc[i][2] * asv[2] + acc[i][3] * asv[3];
            float s2 = acc[i][0] * adv[0] + acc[i][1] * adv[1] + acc[i][2] * adv[2] + acc[i][3] * adv[3];
            sSD[rg * 8 + i][cg] = make_float2(s1, s2);
        }
        if (r < M) {
            float v0 = acc[i][0] + bv[0];
            float v1 = acc[i][1] + bv[1];
            float v2 = acc[i][2] + bv[2];
            float v3 = acc[i][3] + bv[3];
            if (ACT) { v0 = lrelu01(v0); v1 = lrelu01(v1); v2 = lrelu01(v2); v3 = lrelu01(v3); }
            if (SCORES) {
                __half2 h01 = __floats2half2_rn(v0, v1);
                __half2 h23 = __floats2half2_rn(v2, v3);
                uint2 pk = make_uint2(*(unsigned*)&h01, *(unsigned*)&h23);
                *(uint2*)((__half*)Cv + r * 96 + c0) = pk;
            } else {
                *(float4*)((float*)Cv + r * 96 + c0) = make_float4(v0, v1, v2, v3);
            }
        }
    }
    if (SCORES) {
        __syncthreads();
        if (tid < 128) {
            float s1 = 0.f, s2 = 0.f;
            #pragma unroll
            for (int c = 0; c < 24; c++) {
                float2 v = sSD[tid][c];
                s1 += v.x; s2 += v.y;
            }
            int r = rowBase + tid;
            if (r < M) { ssO[r] = s1; sdO[r] = s2; }
        }
    }
}

// ---------------- GAT aggregation: batched-shfl csr, half2 gather ------------
// lane l owns channels {2l,2l+1} and (l<16) {64+2l,65+2l}.
// 32 edge indices fetched per coalesced LDG, broadcast via shfl.
__global__ __launch_bounds__(512) void agg_k(
    const __half* __restrict__ hp,
    const float* __restrict__ ss, const float* __restrict__ sd,
    const float* __restrict__ bias, float* __restrict__ out,
    float* __restrict__ sumP, float* __restrict__ sqP)
{
    __shared__ float bw0[16][96];
    __shared__ float bw1[16][96];
    int tid = threadIdx.x;
    int warp = tid >> 5, lane = tid & 31;
    int d = (blockIdx.x * blockDim.x + tid) >> 5;
    float2 v01 = make_float2(0.f, 0.f);
    float2 v23 = make_float2(0.f, 0.f);
    if (d < Nn) {
        int s0 = g_rs[d], s1e = g_rs[d + 1];
        float sdd = sd[d];
        float dA = 0.f, dB = 0.f;
        float2 a01A = make_float2(0.f, 0.f), a01B = make_float2(0.f, 0.f);
        float2 a23A = make_float2(0.f, 0.f), a23B = make_float2(0.f, 0.f);
        for (int j = s0; j < s1e; j += 32) {
            int bn = min(32, s1e - j);
            int myIdx = (j + lane < s1e) ? g_csr[j + lane] : 0;   // coalesced
            int k = 0;
            for (; k + 2 <= bn; k += 2) {
                int sA = __shfl_sync(0xffffffffu, myIdx, k);
                int sB = __shfl_sync(0xffffffffu, myIdx, k + 1);
                float eA = ss[sA] + sdd;
                float eB = ss[sB] + sdd;
                eA = (eA >= 0.f) ? eA : 0.2f * eA;
                eB = (eB >= 0.f) ? eB : 0.2f * eB;
                float wA = __expf(eA), wB = __expf(eB);
                const __half2* rA = (const __half2*)(hp + (size_t)sA * 96);
                const __half2* rB = (const __half2*)(hp + (size_t)sB * 96);
                float2 pA0 = __half22float2(rA[lane]);
                float2 pB0 = __half22float2(rB[lane]);
                dA += wA;  dB += wB;
                a01A.x = fmaf(wA, pA0.x, a01A.x);
                a01A.y = fmaf(wA, pA0.y, a01A.y);
                a01B.x = fmaf(wB, pB0.x, a01B.x);
                a01B.y = fmaf(wB, pB0.y, a01B.y);
                if (lane < 16) {
                    float2 pA1 = __half22float2(rA[32 + lane]);
                    float2 pB1 = __half22float2(rB[32 + lane]);
                    a23A.x = fmaf(wA, pA1.x, a23A.x);
                    a23A.y = fmaf(wA, pA1.y, a23A.y);
                    a23B.x = fmaf(wB, pB1.x, a23B.x);
                    a23B.y = fmaf(wB, pB1.y, a23B.y);
                }
            }
            if (k < bn) {
                int sA = __shfl_sync(0xffffffffu, myIdx, k);
                float eA = ss[sA] + sdd;
                eA = (eA >= 0.f) ? eA : 0.2f * eA;
                float wA = __expf(eA);
                const __half2* rA = (const __half2*)(hp + (size_t)sA * 96);
                float2 pA0 = __half22float2(rA[lane]);
                dA += wA;
                a01A.x = fmaf(wA, pA0.x, a01A.x);
                a01A.y = fmaf(wA, pA0.y, a01A.y);
                if (lane < 16) {
                    float2 pA1 = __half22float2(rA[32 + lane]);
                    a23A.x = fmaf(wA, pA1.x, a23A.x);
                    a23A.y = fmaf(wA, pA1.y, a23A.y);
                }
            }
        }
        float inv = 1.f / (dA + dB);
        v01.x = (a01A.x + a01B.x) * inv + bias[2 * lane];
        v01.y = (a01A.y + a01B.y) * inv + bias[2 * lane + 1];
        *(float2*)&out[d * 96 + 2 * lane] = v01;
        if (lane < 16) {
            v23.x = (a23A.x + a23B.x) * inv + bias[64 + 2 * lane];
            v23.y = (a23A.y + a23B.y) * inv + bias[65 + 2 * lane];
            *(float2*)&out[d * 96 + 64 + 2 * lane] = v23;
        }
    }
    // atomic-free BN stats: per-warp channel partials (lane owns its channels)
    *(float2*)&bw0[warp][2 * lane] = v01;
    *(float2*)&bw1[warp][2 * lane] = make_float2(v01.x * v01.x, v01.y * v01.y);
    if (lane < 16) {
        *(float2*)&bw0[warp][64 + 2 * lane] = v23;
        *(float2*)&bw1[warp][64 + 2 * lane] = make_float2(v23.x * v23.x, v23.y * v23.y);
    } else if (d >= Nn || true) {
        // channels 64..95 written only by lanes 0..15 (above); nothing else needed
    }
    __syncthreads();
    if (tid < 96) {
        float s = 0.f, q = 0.f;
        #pragma unroll
        for (int w = 0; w < 16; w++) { s += bw0[w][tid]; q += bw1[w][tid]; }
        atomicAdd(&sumP[tid], s);
        atomicAdd(&sqP[tid], q);
    }
}

// ---------------- fused BN-apply + Poincare expmap0 + segment pooling ----------------
__global__ void expool_k(const float* __restrict__ t, const float* __restrict__ idn,
                         const float* __restrict__ gma, const float* __restrict__ bta,
                         const float* __restrict__ sumP, const float* __restrict__ sqP,
                         const int* __restrict__ batch)
{
    __shared__ float sp[Gg * Hh];
    __shared__ float scn[Gg];
    __shared__ float s_sc[96], s_sh[96];
    if (threadIdx.x < 96) {
        int c = threadIdx.x;
        float mu = sumP[c] * (1.f / Nn);
        float var = sqP[c] * (1.f / Nn) - mu * mu;
        float is = rsqrtf(var + BNEPS);
        float gv = gma[c];
        s_sc[c] = gv * is;
        s_sh[c] = bta[c] - mu * gv * is;
    }
    for (int i = threadIdx.x; i < Gg * Hh; i += blockDim.x) sp[i] = 0.f;
    if (threadIdx.x < Gg) scn[threadIdx.x] = 0.f;
    __syncthreads();
    int lane = threadIdx.x & 31;
    int warp = (blockIdx.x * blockDim.x + threadIdx.x) >> 5;
    int nwarps = (gridDim.x * blockDim.x) >> 5;
    for (int n = warp; n < Nn; n += nwarps) {
        float v0 = lrelu01(fmaf(t[n * 96 + lane],      s_sc[lane],      s_sh[lane]))      + idn[n * 96 + lane];
        float v1 = lrelu01(fmaf(t[n * 96 + lane + 32], s_sc[lane + 32], s_sh[lane + 32])) + idn[n * 96 + lane + 32];
        float v2 = lrelu01(fmaf(t[n * 96 + lane + 64], s_sc[lane + 64], s_sh[lane + 64])) + idn[n * 96 + lane + 64];
        float q = v0 * v0 + v1 * v1 + v2 * v2;
        #pragma unroll
        for (int o = 16; o; o >>= 1) q += __shfl_xor_sync(0xffffffffu, q, o);
        float nrm = fmaxf(sqrtf(q), 1e-15f);
        float s = tanhf(nrm) / nrm;
        int g = batch[n];
        atomicAdd(&sp[g * 96 + lane], v0 * s);
        atomicAdd(&sp[g * 96 + lane + 32], v1 * s);
        atomicAdd(&sp[g * 96 + lane + 64], v2 * s);
        if (lane == 0) atomicAdd(&scn[g], 1.f);
    }
    __syncthreads();
    for (int i = threadIdx.x; i < Gg * Hh; i += blockDim.x) atomicAdd(&g_pooled[i], sp[i]);
    if (threadIdx.x < Gg) atomicAdd(&g_cnt[threadIdx.x], scn[threadIdx.x]);
}

// ---------------- head ----------------
__global__ void head_k(const float* __restrict__ fc3W, const float* __restrict__ fc3b,
                       const float* __restrict__ fc4W, const float* __restrict__ fc4b,
                       float* __restrict__ out)
{
    __shared__ float p[Gg * Hh];
    __shared__ float o1[Gg * 48];
    for (int i = threadIdx.x; i < Gg * Hh; i += blockDim.x) {
        int g = i / 96;
        p[i] = g_pooled[i] / fmaxf(g_cnt[g], 1.f);
    }
    __syncthreads();
    for (int i = threadIdx.x; i < Gg * 48; i += blockDim.x) {
        int g = i / 48, c = i % 48;
        float a = fc3b[c];
        for (int k = 0; k < 96; k++) a = fmaf(p[g * 96 + k], fc3W[k * 48 + c], a);
        o1[i] = lrelu01(a);
    }
    __syncthreads();
    for (int i = threadIdx.x; i < Gg * NCLS; i += blockDim.x) {
        int g = i / NCLS, c = i % NCLS;
        float a = fc4b[c];
        for (int k = 0; k < 48; k++) a = fmaf(o1[g * 48 + k], fc4W[k * NCLS + c], a);
        out[i] = a;
    }
}

// ---------------- launch ----------------
extern "C" void kernel_launch(void* const* d_in, const int* in_sizes, int n_in,
                              void* d_out, int out_size)
{
    const float* x     = (const float*)d_in[0];
    const int*   ei    = (const int*)d_in[1];
    const int*   batch = (const int*)d_in[2];
    const float* embW  = (const float*)d_in[3];
    const float* embB  = (const float*)d_in[4];
    const float* cW[3]  = {(const float*)d_in[5],  (const float*)d_in[9],  (const float*)d_in[13]};
    const float* cAS[3] = {(const float*)d_in[6],  (const float*)d_in[10], (const float*)d_in[14]};
    const float* cAD[3] = {(const float*)d_in[7],  (const float*)d_in[11], (const float*)d_in[15]};
    const float* cB[3]  = {(const float*)d_in[8],  (const float*)d_in[12], (const float*)d_in[16]};
    const float* fcW[2] = {(const float*)d_in[17], (const float*)d_in[19]};
    const float* fcB[2] = {(const float*)d_in[18], (const float*)d_in[20]};
    const float* bnG[3] = {(const float*)d_in[21], (const float*)d_in[23], (const float*)d_in[25]};
    const float* bnB[3] = {(const float*)d_in[22], (const float*)d_in[24], (const float*)d_in[26]};
    const float* fc3W = (const float*)d_in[27];
    const float* fc3b = (const float*)d_in[28];
    const float* fc4W = (const float*)d_in[29];
    const float* fc4b = (const float*)d_in[30];
    float* out = (float*)d_out;

    float *ph, *pid, *ptmp, *pss, *psd, *pbs, *pbq;
    __half* phph;
    cudaGetSymbolAddress((void**)&ph,   g_h);
    cudaGetSymbolAddress((void**)&pid,  g_id);
    cudaGetSymbolAddress((void**)&phph, g_hph);
    cudaGetSymbolAddress((void**)&ptmp, g_tmp);
    cudaGetSymbolAddress((void**)&pss,  g_ss);
    cudaGetSymbolAddress((void**)&psd,  g_sd);
    cudaGetSymbolAddress((void**)&pbs,  g_bnsum);
    cudaGetSymbolAddress((void**)&pbq,  g_bnsq);

    const int EB = (ETOT + 255) / 256;
    const int GB = (Nn + 127) / 128;
    const int AB = (Nn * 32 + 511) / 512;

    cudaFuncSetAttribute(gemm96w<0, 0, 1>, cudaFuncAttributeMaxDynamicSharedMemorySize, DSM96);
    cudaFuncSetAttribute(gemm96w<1, 1, 0>, cudaFuncAttributeMaxDynamicSharedMemorySize, DSM96);

    // Fork: CSR build concurrent with embed GEMM. Streams/events intentionally
    // leaked (destroying them mid-capture would abort graph capture).
    cudaStream_t s1;
    cudaStreamCreateWithFlags(&s1, cudaStreamNonBlocking);
    cudaEvent_t evFork, evJoin;
    cudaEventCreateWithFlags(&evFork, cudaEventDisableTiming);
    cudaEventCreateWithFlags(&evJoin, cudaEventDisableTiming);

    cudaEventRecord(evFork, 0);
    cudaStreamWaitEvent(s1, evFork, 0);
    zero_k<<<256, 256, 0, s1>>>();
    count_k<<<EB, 256, 0, s1>>>(ei);
    scan_k<<<1, 1024, 0, s1>>>();
    scatter_k<<<EB, 256, 0, s1>>>(ei);
    cudaEventRecord(evJoin, s1);

    // embed: h = lrelu(x @ embW + embB); identity = h
    gemm128_emb<<<GB, 384>>>(x, embW, embB, ph, pid, Nn, 256);

    for (int l = 0; l < 3; l++) {
        // hp(fp16) = h @ cW  (+ fused atomic-free attention scores)
        gemm96w<0, 0, 1><<<GB, 384, DSM96>>>(ph, nullptr, nullptr, nullptr, nullptr, nullptr,
                                             cW[l], nullptr, cAS[l], cAD[l], pss, psd,
                                             (void*)phph, Nn);
        if (l == 0) cudaStreamWaitEvent(0, evJoin, 0);   // CSR + zeroed BN slots ready
        agg_k<<<AB, 512>>>(phph, pss, psd, cB[l], ptmp, pbs + l * Hh, pbq + l * Hh);
        if (l < 2) {
            // h = lrelu( (lrelu(bn(tmp)) + id) @ fcW + fcB ) — BN fused into A-load
            gemm96w<1, 1, 0><<<GB, 384, DSM96>>>(ptmp, pid, bnG[l], bnB[l], pbs + l * Hh, pbq + l * Hh,
                                                 fcW[l], fcB[l], nullptr, nullptr, nullptr, nullptr,
                                                 (void*)ph, Nn);
        }
    }

    expool_k<<<160, 256>>>(ptmp, pid, bnG[2], bnB[2], pbs + 2 * Hh, pbq + 2 * Hh, batch);
    head_k<<<1, 256>>>(fc3W, fc3b, fc4W, fc4b, out);
}

// round 16
// speedup vs baseline: 1.0165x; 1.0165x over previous
#include <cuda_runtime.h>
#include <cuda_fp16.h>
#include <math.h>

#define Nn 50000
#define Ee 800000
#define ETOT 850000
#define Hh 96
#define Gg 64
#define NCLS 4
#define BNEPS 1e-5f

// ---------------- device scratch ----------------
__device__ float g_h[Nn * Hh];
__device__ float g_id[Nn * Hh];
__device__ __half g_hph[Nn * Hh];    // hp in fp16
__device__ float g_tmp[Nn * Hh];
__device__ float g_ss[Nn], g_sd[Nn];
__device__ int   g_deg[Nn];
__device__ int   g_rs[Nn + 1];
__device__ int   g_cur[Nn];
__device__ int   g_csr[ETOT];
__device__ float g_bnsum[3 * Hh], g_bnsq[3 * Hh];
__device__ float g_pooled[Gg * Hh];
__device__ float g_cnt[Gg];

__device__ __forceinline__ float lrelu01(float v) { return v >= 0.f ? v : 0.01f * v; }

// ---------------- zero / init ----------------
__global__ void zero_k() {
    int i = blockIdx.x * blockDim.x + threadIdx.x;
    int stride = gridDim.x * blockDim.x;
    for (int j = i; j < Nn; j += stride) g_deg[j] = 0;
    if (i < Gg * Hh) g_pooled[i] = 0.f;
    if (i < Gg) g_cnt[i] = 0.f;
    if (i < 3 * Hh) { g_bnsum[i] = 0.f; g_bnsq[i] = 0.f; }
}

// ---------------- CSR build ----------------
__global__ void count_k(const int* __restrict__ ei) {
    int i = blockIdx.x * blockDim.x + threadIdx.x;
    if (i >= ETOT) return;
    int d = (i < Ee) ? ei[Ee + i] : (i - Ee);
    atomicAdd(&g_deg[d], 1);
}

__global__ void scan_k() {
    __shared__ int part[1024];
    int t = threadIdx.x;
    const int CH = (Nn + 1023) / 1024;
    int base = t * CH;
    int s = 0;
    for (int i = 0; i < CH; i++) {
        int idx = base + i;
        if (idx < Nn) s += g_deg[idx];
    }
    part[t] = s;
    __syncthreads();
    for (int off = 1; off < 1024; off <<= 1) {
        int v = (t >= off) ? part[t - off] : 0;
        __syncthreads();
        part[t] += v;
        __syncthreads();
    }
    int run = (t == 0) ? 0 : part[t - 1];
    for (int i = 0; i < CH; i++) {
        int idx = base + i;
        if (idx < Nn) {
            g_rs[idx] = run;
            g_cur[idx] = run;
            run += g_deg[idx];
        }
    }
    if (t == blockDim.x - 1) g_rs[Nn] = part[blockDim.x - 1];
}

__global__ void scatter_k(const int* __restrict__ ei) {
    int i = blockIdx.x * blockDim.x + threadIdx.x;
    if (i >= ETOT) return;
    int sN, dN;
    if (i < Ee) { sN = ei[i]; dN = ei[Ee + i]; }
    else        { sN = i - Ee; dN = i - Ee; }
    int pos = atomicAdd(&g_cur[dN], 1);
    g_csr[pos] = sN;
}

// ---------------- embed GEMM (K=256): proven gemm128 core ----------------
__global__ __launch_bounds__(384, 2) void gemm128_emb(
    const float* __restrict__ A, const float* __restrict__ W,
    const float* __restrict__ bias,
    float* __restrict__ C, float* __restrict__ C2, int M, int K)
{
    __shared__ __align__(16) float Ash[32][132];
    __shared__ float Wsh[32][96];
    int tid = threadIdx.x;
    int cg = tid % 24;
    int rg = tid / 24;
    int rowBase = blockIdx.x * 128;
    float acc[8][4] = {};
    for (int kc = 0; kc < K; kc += 32) {
        for (int idx = tid; idx < 1024; idx += 384) {
            int m = idx >> 3, kq = idx & 7;
            int r = rowBase + m;
            float4 v = make_float4(0.f, 0.f, 0.f, 0.f);
            if (r < M) v = *(const float4*)&A[r * K + kc + kq * 4];
            int k0 = kq * 4;
            Ash[k0 + 0][m] = v.x;
            Ash[k0 + 1][m] = v.y;
            Ash[k0 + 2][m] = v.z;
            Ash[k0 + 3][m] = v.w;
        }
        #pragma unroll
        for (int j = 0; j < 8; j++) {
            int idx = tid + j * 384;
            int k = idx / 96, c = idx % 96;
            Wsh[k][c] = W[(kc + k) * 96 + c];
        }
        __syncthreads();
        #pragma unroll
        for (int k = 0; k < 32; k++) {
            float4 al = *(const float4*)&Ash[k][rg * 8];
            float4 ah = *(const float4*)&Ash[k][rg * 8 + 4];
            float4 w  = *(const float4*)&Wsh[k][cg * 4];
            float av[8] = {al.x, al.y, al.z, al.w, ah.x, ah.y, ah.z, ah.w};
            float wv[4] = {w.x, w.y, w.z, w.w};
            #pragma unroll
            for (int i = 0; i < 8; i++)
                #pragma unroll
                for (int j = 0; j < 4; j++)
                    acc[i][j] = fmaf(av[i], wv[j], acc[i][j]);
        }
        __syncthreads();
    }
    int c0 = cg * 4;
    float bv[4];
    #pragma unroll
    for (int j = 0; j < 4; j++) bv[j] = bias[c0 + j];
    int r0 = rowBase + rg * 8;
    #pragma unroll
    for (int i = 0; i < 8; i++) {
        int r = r0 + i;
        if (r < M) {
            float v0 = lrelu01(acc[i][0] + bv[0]);
            float v1 = lrelu01(acc[i][1] + bv[1]);
            float v2 = lrelu01(acc[i][2] + bv[2]);
            float v3 = lrelu01(acc[i][3] + bv[3]);
            float4 o = make_float4(v0, v1, v2, v3);
            *(float4*)&C[r * 96 + c0] = o;
            *(float4*)&C2[r * 96 + c0] = o;
        }
    }
}

// ---------------- K=96 GEMM: W resident + double-buffered A ----------------
#define DSM96 (96 * 96 * 4 + 2 * 32 * 132 * 4)   // 70656
template <int ACT, int MODE, int SCORES>
__global__ __launch_bounds__(384, 2) void gemm96w(
    const float* __restrict__ A, const float* __restrict__ A2,
    const float* __restrict__ gma, const float* __restrict__ bta,
    const float* __restrict__ sumP, const float* __restrict__ sqP,
    const float* __restrict__ W, const float* __restrict__ bias,
    const float* __restrict__ as_, const float* __restrict__ ad_,
    float* __restrict__ ssO, float* __restrict__ sdO,
    void* __restrict__ Cv, int M)
{
    extern __shared__ __align__(16) float dsm[];
    float* Wsh = dsm;                                  // [96*96]
    float (*Ash)[32][132] = (float (*)[32][132])(dsm + 9216);   // [2][32][132]
    float2 (*sSD)[25] = (float2 (*)[25])(dsm + 9216);  // reuses Ash region
    __shared__ float s_sc[96], s_sh[96];
    int tid = threadIdx.x;
    #pragma unroll
    for (int j = 0; j < 24; j++) Wsh[tid + j * 384] = W[tid + j * 384];
    if (MODE == 1) {
        if (tid < 96) {
            float mu = sumP[tid] * (1.f / Nn);
            float var = sqP[tid] * (1.f / Nn) - mu * mu;
            float is = rsqrtf(var + BNEPS);
            float gv = gma[tid];
            s_sc[tid] = gv * is;
            s_sh[tid] = bta[tid] - mu * gv * is;
        }
        __syncthreads();
    }
    int cg = tid % 24;
    int rg = tid / 24;
    int rowBase = blockIdx.x * 128;
    float acc[8][4] = {};
    float4 pf[3];

    auto loadA = [&](int kc) {
        #pragma unroll
        for (int it = 0; it < 3; it++) {
            int idx = tid + it * 384;
            if (idx < 1024) {
                int m = idx >> 3, kq = idx & 7;
                int r = rowBase + m;
                float4 v = make_float4(0.f, 0.f, 0.f, 0.f);
                if (r < M) {
                    v = *(const float4*)&A[r * 96 + kc + kq * 4];
                    if (MODE == 1) {
                        float4 u = *(const float4*)&A2[r * 96 + kc + kq * 4];
                        int c = kc + kq * 4;
                        v.x = lrelu01(fmaf(v.x, s_sc[c + 0], s_sh[c + 0])) + u.x;
                        v.y = lrelu01(fmaf(v.y, s_sc[c + 1], s_sh[c + 1])) + u.y;
                        v.z = lrelu01(fmaf(v.z, s_sc[c + 2], s_sh[c + 2])) + u.z;
                        v.w = lrelu01(fmaf(v.w, s_sc[c + 3], s_sh[c + 3])) + u.w;
                    }
                }
                pf[it] = v;
            }
        }
    };
    auto stsA = [&](int buf) {
        #pragma unroll
        for (int it = 0; it < 3; it++) {
            int idx = tid + it * 384;
            if (idx < 1024) {
                int m = idx >> 3, kq = idx & 7;
                int k0 = kq * 4;
                Ash[buf][k0 + 0][m] = pf[it].x;
                Ash[buf][k0 + 1][m] = pf[it].y;
                Ash[buf][k0 + 2][m] = pf[it].z;
                Ash[buf][k0 + 3][m] = pf[it].w;
            }
        }
    };

    loadA(0);
    stsA(0);
    __syncthreads();
    #pragma unroll
    for (int c = 0; c < 3; c++) {
        if (c < 2) loadA((c + 1) * 32);
        int buf = c & 1;
        const float* wrow = Wsh + c * 32 * 96 + cg * 4;
        #pragma unroll
        for (int k = 0; k < 32; k++) {
            float4 al = *(const float4*)&Ash[buf][k][rg * 8];
            float4 ah = *(const float4*)&Ash[buf][k][rg * 8 + 4];
            float4 w  = *(const float4*)(wrow + k * 96);
            float av[8] = {al.x, al.y, al.z, al.w, ah.x, ah.y, ah.z, ah.w};
            float wv[4] = {w.x, w.y, w.z, w.w};
            #pragma unroll
            for (int i = 0; i < 8; i++)
                #pragma unroll
                for (int j = 0; j < 4; j++)
                    acc[i][j] = fmaf(av[i], wv[j], acc[i][j]);
        }
        if (c < 2) {
            stsA(buf ^ 1);
            __syncthreads();
        }
    }
    __syncthreads();   // Ash dead; safe to alias as sSD

    int c0 = cg * 4;
    float bv[4];
    #pragma unroll
    for (int j = 0; j < 4; j++) bv[j] = bias ? bias[c0 + j] : 0.f;
    float asv[4], adv[4];
    if (SCORES) {
        #pragma unroll
        for (int j = 0; j < 4; j++) { asv[j] = as_[c0 + j]; adv[j] = ad_[c0 + j]; }
    }
    int r0 = rowBase + rg * 8;
    #pragma unroll
    for (int i = 0; i < 8; i++) {
        int r = r0 + i;
        if (SCORES) {
            float s1 = acc[i][0] * asv[0] + acc[i][1] * asv[1] + acc[i][2] * asv[2] + acc[i][3] * asv[3];
            float s2 = acc[i][0] * adv[0] + acc[i][1] * adv[1] + acc[i][2] * adv[2] + acc[i][3] * adv[3];
            sSD[rg * 8 + i][cg] = make_float2(s1, s2);
        }
        if (r < M) {
            float v0 = acc[i][0] + bv[0];
            float v1 = acc[i][1] + bv[1];
            float v2 = acc[i][2] + bv[2];
            float v3 = acc[i][3] + bv[3];
            if (ACT) { v0 = lrelu01(v0); v1 = lrelu01(v1); v2 = lrelu01(v2); v3 = lrelu01(v3); }
            if (SCORES) {
                __half2 h01 = __floats2half2_rn(v0, v1);
                __half2 h23 = __floats2half2_rn(v2, v3);
                uint2 pk = make_uint2(*(unsigned*)&h01, *(unsigned*)&h23);
                *(uint2*)((__half*)Cv + r * 96 + c0) = pk;
            } else {
                *(float4*)((float*)Cv + r * 96 + c0) = make_float4(v0, v1, v2, v3);
            }
        }
    }
    if (SCORES) {
        __syncthreads();
        if (tid < 128) {
            float s1 = 0.f, s2 = 0.f;
            #pragma unroll
            for (int c = 0; c < 24; c++) {
                float2 v = sSD[tid][c];
                s1 += v.x; s2 += v.y;
            }
            int r = rowBase + tid;
            if (r < M) { ssO[r] = s1; sdO[r] = s2; }
        }
    }
}

// ---------------- GAT aggregation: uniform csr broadcast + half2 gather ------
// R13 loop structure (proven); lane l owns channels {2l,2l+1} and (lane<16)
// {64+2l,65+2l} -> hp costs 2 warp-LDGs per edge instead of 3.
__global__ __launch_bounds__(512) void agg_k(
    const __half* __restrict__ hp,
    const float* __restrict__ ss, const float* __restrict__ sd,
    const float* __restrict__ bias, float* __restrict__ out,
    float* __restrict__ sumP, float* __restrict__ sqP)
{
    __shared__ float bw0[16][96];
    __shared__ float bw1[16][96];
    int tid = threadIdx.x;
    int warp = tid >> 5, lane = tid & 31;
    int d = (blockIdx.x * blockDim.x + tid) >> 5;
    float2 v01 = make_float2(0.f, 0.f);
    float2 v23 = make_float2(0.f, 0.f);
    if (d < Nn) {
        int j = g_rs[d], s1e = g_rs[d + 1];
        float sdd = sd[d];
        float dA = 0.f, dB = 0.f;
        float2 a01A = make_float2(0.f, 0.f), a01B = make_float2(0.f, 0.f);
        float2 a23A = make_float2(0.f, 0.f), a23B = make_float2(0.f, 0.f);
        for (; j + 2 <= s1e; j += 2) {
            int sA = g_csr[j], sB = g_csr[j + 1];      // warp-uniform broadcast
            float eA = ss[sA] + sdd;
            float eB = ss[sB] + sdd;
            eA = (eA >= 0.f) ? eA : 0.2f * eA;
            eB = (eB >= 0.f) ? eB : 0.2f * eB;
            float wA = __expf(eA), wB = __expf(eB);
            const __half2* rA = (const __half2*)(hp + (size_t)sA * 96);
            const __half2* rB = (const __half2*)(hp + (size_t)sB * 96);
            float2 pA0 = __half22float2(rA[lane]);
            float2 pB0 = __half22float2(rB[lane]);
            dA += wA;  dB += wB;
            a01A.x = fmaf(wA, pA0.x, a01A.x);
            a01A.y = fmaf(wA, pA0.y, a01A.y);
            a01B.x = fmaf(wB, pB0.x, a01B.x);
            a01B.y = fmaf(wB, pB0.y, a01B.y);
            if (lane < 16) {
                float2 pA1 = __half22float2(rA[32 + lane]);
                float2 pB1 = __half22float2(rB[32 + lane]);
                a23A.x = fmaf(wA, pA1.x, a23A.x);
                a23A.y = fmaf(wA, pA1.y, a23A.y);
                a23B.x = fmaf(wB, pB1.x, a23B.x);
                a23B.y = fmaf(wB, pB1.y, a23B.y);
            }
        }
        if (j < s1e) {
            int sA = g_csr[j];
            float eA = ss[sA] + sdd;
            eA = (eA >= 0.f) ? eA : 0.2f * eA;
            float wA = __expf(eA);
            const __half2* rA = (const __half2*)(hp + (size_t)sA * 96);
            float2 pA0 = __half22float2(rA[lane]);
            dA += wA;
            a01A.x = fmaf(wA, pA0.x, a01A.x);
            a01A.y = fmaf(wA, pA0.y, a01A.y);
            if (lane < 16) {
                float2 pA1 = __half22float2(rA[32 + lane]);
                a23A.x = fmaf(wA, pA1.x, a23A.x);
                a23A.y = fmaf(wA, pA1.y, a23A.y);
            }
        }
        float inv = 1.f / (dA + dB);
        v01.x = (a01A.x + a01B.x) * inv + bias[2 * lane];
        v01.y = (a01A.y + a01B.y) * inv + bias[2 * lane + 1];
        *(float2*)&out[d * 96 + 2 * lane] = v01;
        if (lane < 16) {
            v23.x = (a23A.x + a23B.x) * inv + bias[64 + 2 * lane];
            v23.y = (a23A.y + a23B.y) * inv + bias[65 + 2 * lane];
            *(float2*)&out[d * 96 + 64 + 2 * lane] = v23;
        }
    }
    // atomic-free BN stats: per-warp channel partials (lane owns its channels)
    *(float2*)&bw0[warp][2 * lane] = v01;
    *(float2*)&bw1[warp][2 * lane] = make_float2(v01.x * v01.x, v01.y * v01.y);
    if (lane < 16) {
        *(float2*)&bw0[warp][64 + 2 * lane] = v23;
        *(float2*)&bw1[warp][64 + 2 * lane] = make_float2(v23.x * v23.x, v23.y * v23.y);
    }
    __syncthreads();
    if (tid < 96) {
        float s = 0.f, q = 0.f;
        #pragma unroll
        for (int w = 0; w < 16; w++) { s += bw0[w][tid]; q += bw1[w][tid]; }
        atomicAdd(&sumP[tid], s);
        atomicAdd(&sqP[tid], q);
    }
}

// ---------------- fused BN-apply + Poincare expmap0 + segment pooling ----------------
__global__ void expool_k(const float* __restrict__ t, const float* __restrict__ idn,
                         const float* __restrict__ gma, const float* __restrict__ bta,
                         const float* __restrict__ sumP, const float* __restrict__ sqP,
                         const int* __restrict__ batch)
{
    __shared__ float sp[Gg * Hh];
    __shared__ float scn[Gg];
    __shared__ float s_sc[96], s_sh[96];
    if (threadIdx.x < 96) {
        int c = threadIdx.x;
        float mu = sumP[c] * (1.f / Nn);
        float var = sqP[c] * (1.f / Nn) - mu * mu;
        float is = rsqrtf(var + BNEPS);
        float gv = gma[c];
        s_sc[c] = gv * is;
        s_sh[c] = bta[c] - mu * gv * is;
    }
    for (int i = threadIdx.x; i < Gg * Hh; i += blockDim.x) sp[i] = 0.f;
    if (threadIdx.x < Gg) scn[threadIdx.x] = 0.f;
    __syncthreads();
    int lane = threadIdx.x & 31;
    int warp = (blockIdx.x * blockDim.x + threadIdx.x) >> 5;
    int nwarps = (gridDim.x * blockDim.x) >> 5;
    for (int n = warp; n < Nn; n += nwarps) {
        float v0 = lrelu01(fmaf(t[n * 96 + lane],      s_sc[lane],      s_sh[lane]))      + idn[n * 96 + lane];
        float v1 = lrelu01(fmaf(t[n * 96 + lane + 32], s_sc[lane + 32], s_sh[lane + 32])) + idn[n * 96 + lane + 32];
        float v2 = lrelu01(fmaf(t[n * 96 + lane + 64], s_sc[lane + 64], s_sh[lane + 64])) + idn[n * 96 + lane + 64];
        float q = v0 * v0 + v1 * v1 + v2 * v2;
        #pragma unroll
        for (int o = 16; o; o >>= 1) q += __shfl_xor_sync(0xffffffffu, q, o);
        float nrm = fmaxf(sqrtf(q), 1e-15f);
        float s = tanhf(nrm) / nrm;
        int g = batch[n];
        atomicAdd(&sp[g * 96 + lane], v0 * s);
        atomicAdd(&sp[g * 96 + lane + 32], v1 * s);
        atomicAdd(&sp[g * 96 + lane + 64], v2 * s);
        if (lane == 0) atomicAdd(&scn[g], 1.f);
    }
    __syncthreads();
    for (int i = threadIdx.x; i < Gg * Hh; i += blockDim.x) atomicAdd(&g_pooled[i], sp[i]);
    if (threadIdx.x < Gg) atomicAdd(&g_cnt[threadIdx.x], scn[threadIdx.x]);
}

// ---------------- head ----------------
__global__ void head_k(const float* __restrict__ fc3W, const float* __restrict__ fc3b,
                       const float* __restrict__ fc4W, const float* __restrict__ fc4b,
                       float* __restrict__ out)
{
    __shared__ float p[Gg * Hh];
    __shared__ float o1[Gg * 48];
    for (int i = threadIdx.x; i < Gg * Hh; i += blockDim.x) {
        int g = i / 96;
        p[i] = g_pooled[i] / fmaxf(g_cnt[g], 1.f);
    }
    __syncthreads();
    for (int i = threadIdx.x; i < Gg * 48; i += blockDim.x) {
        int g = i / 48, c = i % 48;
        float a = fc3b[c];
        for (int k = 0; k < 96; k++) a = fmaf(p[g * 96 + k], fc3W[k * 48 + c], a);
        o1[i] = lrelu01(a);
    }
    __syncthreads();
    for (int i = threadIdx.x; i < Gg * NCLS; i += blockDim.x) {
        int g = i / NCLS, c = i % NCLS;
        float a = fc4b[c];
        for (int k = 0; k < 48; k++) a = fmaf(o1[g * 48 + k], fc4W[k * NCLS + c], a);
        out[i] = a;
    }
}

// ---------------- launch ----------------
extern "C" void kernel_launch(void* const* d_in, const int* in_sizes, int n_in,
                              void* d_out, int out_size)
{
    const float* x     = (const float*)d_in[0];
    const int*   ei    = (const int*)d_in[1];
    const int*   batch = (const int*)d_in[2];
    const float* embW  = (const float*)d_in[3];
    const float* embB  = (const float*)d_in[4];
    const float* cW[3]  = {(const float*)d_in[5],  (const float*)d_in[9],  (const float*)d_in[13]};
    const float* cAS[3] = {(const float*)d_in[6],  (const float*)d_in[10], (const float*)d_in[14]};
    const float* cAD[3] = {(const float*)d_in[7],  (const float*)d_in[11], (const float*)d_in[15]};
    const float* cB[3]  = {(const float*)d_in[8],  (const float*)d_in[12], (const float*)d_in[16]};
    const float* fcW[2] = {(const float*)d_in[17], (const float*)d_in[19]};
    const float* fcB[2] = {(const float*)d_in[18], (const float*)d_in[20]};
    const float* bnG[3] = {(const float*)d_in[21], (const float*)d_in[23], (const float*)d_in[25]};
    const float* bnB[3] = {(const float*)d_in[22], (const float*)d_in[24], (const float*)d_in[26]};
    const float* fc3W = (const float*)d_in[27];
    const float* fc3b = (const float*)d_in[28];
    const float* fc4W = (const float*)d_in[29];
    const float* fc4b = (const float*)d_in[30];
    float* out = (float*)d_out;

    float *ph, *pid, *ptmp, *pss, *psd, *pbs, *pbq;
    __half* phph;
    cudaGetSymbolAddress((void**)&ph,   g_h);
    cudaGetSymbolAddress((void**)&pid,  g_id);
    cudaGetSymbolAddress((void**)&phph, g_hph);
    cudaGetSymbolAddress((void**)&ptmp, g_tmp);
    cudaGetSymbolAddress((void**)&pss,  g_ss);
    cudaGetSymbolAddress((void**)&psd,  g_sd);
    cudaGetSymbolAddress((void**)&pbs,  g_bnsum);
    cudaGetSymbolAddress((void**)&pbq,  g_bnsq);

    const int EB = (ETOT + 255) / 256;
    const int GB = (Nn + 127) / 128;
    const int AB = (Nn * 32 + 511) / 512;

    cudaFuncSetAttribute(gemm96w<0, 0, 1>, cudaFuncAttributeMaxDynamicSharedMemorySize, DSM96);
    cudaFuncSetAttribute(gemm96w<1, 1, 0>, cudaFuncAttributeMaxDynamicSharedMemorySize, DSM96);

    // Fork: CSR build concurrent with embed GEMM. Streams/events intentionally
    // leaked (destroying them mid-capture would abort graph capture).
    cudaStream_t s1;
    cudaStreamCreateWithFlags(&s1, cudaStreamNonBlocking);
    cudaEvent_t evFork, evJoin;
    cudaEventCreateWithFlags(&evFork, cudaEventDisableTiming);
    cudaEventCreateWithFlags(&evJoin, cudaEventDisableTiming);

    cudaEventRecord(evFork, 0);
    cudaStreamWaitEvent(s1, evFork, 0);
    zero_k<<<256, 256, 0, s1>>>();
    count_k<<<EB, 256, 0, s1>>>(ei);
    scan_k<<<1, 1024, 0, s1>>>();
    scatter_k<<<EB, 256, 0, s1>>>(ei);
    cudaEventRecord(evJoin, s1);

    // embed: h = lrelu(x @ embW + embB); identity = h
    gemm128_emb<<<GB, 384>>>(x, embW, embB, ph, pid, Nn, 256);

    for (int l = 0; l < 3; l++) {
        // hp(fp16) = h @ cW  (+ fused atomic-free attention scores)
        gemm96w<0, 0, 1><<<GB, 384, DSM96>>>(ph, nullptr, nullptr, nullptr, nullptr, nullptr,
                                             cW[l], nullptr, cAS[l], cAD[l], pss, psd,
                                             (void*)phph, Nn);
        if (l == 0) cudaStreamWaitEvent(0, evJoin, 0);   // CSR + zeroed BN slots ready
        agg_k<<<AB, 512>>>(phph, pss, psd, cB[l], ptmp, pbs + l * Hh, pbq + l * Hh);
        if (l < 2) {
            // h = lrelu( (lrelu(bn(tmp)) + id) @ fcW + fcB ) — BN fused into A-load
            gemm96w<1, 1, 0><<<GB, 384, DSM96>>>(ptmp, pid, bnG[l], bnB[l], pbs + l * Hh, pbq + l * Hh,
                                                 fcW[l], fcB[l], nullptr, nullptr, nullptr, nullptr,
                                                 (void*)ph, Nn);
        }
    }

    expool_k<<<160, 256>>>(ptmp, pid, bnG[2], bnB[2], pbs + 2 * Hh, pbq + 2 * Hh, batch);
    head_k<<<1, 256>>>(fc3W, fc3b, fc4W, fc4b, out);
}

// round 17
// speedup vs baseline: 1.0371x; 1.0203x over previous
#include <cuda_runtime.h>
#include <cuda_fp16.h>
#include <math.h>

#define Nn 50000
#define Ee 800000
#define ETOT 850000
#define Hh 96
#define Gg 64
#define NCLS 4
#define BNEPS 1e-5f

// ---------------- device scratch ----------------
__device__ float g_h[Nn * Hh];
__device__ float g_id[Nn * Hh];
__device__ __half g_hph[Nn * Hh];    // hp in fp16
__device__ float g_tmp[Nn * Hh];
__device__ float g_ss[Nn], g_sd[Nn];
__device__ int   g_deg[Nn];
__device__ int   g_rs[Nn + 1];
__device__ int   g_cur[Nn];
__device__ int   g_csr[ETOT];
__device__ float g_bnsum[3 * Hh], g_bnsq[3 * Hh];
__device__ float g_pooled[Gg * Hh];
__device__ float g_cnt[Gg];

__device__ __forceinline__ float lrelu01(float v) { return v >= 0.f ? v : 0.01f * v; }

// ---------------- zero / init ----------------
__global__ void zero_k() {
    int i = blockIdx.x * blockDim.x + threadIdx.x;
    int stride = gridDim.x * blockDim.x;
    for (int j = i; j < Nn; j += stride) g_deg[j] = 0;
    if (i < Gg * Hh) g_pooled[i] = 0.f;
    if (i < Gg) g_cnt[i] = 0.f;
    if (i < 3 * Hh) { g_bnsum[i] = 0.f; g_bnsq[i] = 0.f; }
}

// ---------------- CSR build ----------------
__global__ void count_k(const int* __restrict__ ei) {
    int i = blockIdx.x * blockDim.x + threadIdx.x;
    if (i >= ETOT) return;
    int d = (i < Ee) ? ei[Ee + i] : (i - Ee);
    atomicAdd(&g_deg[d], 1);
}

__global__ void scan_k() {
    __shared__ int part[1024];
    int t = threadIdx.x;
    const int CH = (Nn + 1023) / 1024;
    int base = t * CH;
    int s = 0;
    for (int i = 0; i < CH; i++) {
        int idx = base + i;
        if (idx < Nn) s += g_deg[idx];
    }
    part[t] = s;
    __syncthreads();
    for (int off = 1; off < 1024; off <<= 1) {
        int v = (t >= off) ? part[t - off] : 0;
        __syncthreads();
        part[t] += v;
        __syncthreads();
    }
    int run = (t == 0) ? 0 : part[t - 1];
    for (int i = 0; i < CH; i++) {
        int idx = base + i;
        if (idx < Nn) {
            g_rs[idx] = run;
            g_cur[idx] = run;
            run += g_deg[idx];
        }
    }
    if (t == blockDim.x - 1) g_rs[Nn] = part[blockDim.x - 1];
}

__global__ void scatter_k(const int* __restrict__ ei) {
    int i = blockIdx.x * blockDim.x + threadIdx.x;
    if (i >= ETOT) return;
    int sN, dN;
    if (i < Ee) { sN = ei[i]; dN = ei[Ee + i]; }
    else        { sN = i - Ee; dN = i - Ee; }
    int pos = atomicAdd(&g_cur[dN], 1);
    g_csr[pos] = sN;
}

// ---------------- embed GEMM (K=256): proven gemm128 core, single output ----
__global__ __launch_bounds__(384, 2) void gemm128_emb(
    const float* __restrict__ A, const float* __restrict__ W,
    const float* __restrict__ bias,
    float* __restrict__ C, int M, int K)
{
    __shared__ __align__(16) float Ash[32][132];
    __shared__ float Wsh[32][96];
    int tid = threadIdx.x;
    int cg = tid % 24;
    int rg = tid / 24;
    int rowBase = blockIdx.x * 128;
    float acc[8][4] = {};
    for (int kc = 0; kc < K; kc += 32) {
        for (int idx = tid; idx < 1024; idx += 384) {
            int m = idx >> 3, kq = idx & 7;
            int r = rowBase + m;
            float4 v = make_float4(0.f, 0.f, 0.f, 0.f);
            if (r < M) v = *(const float4*)&A[r * K + kc + kq * 4];
            int k0 = kq * 4;
            Ash[k0 + 0][m] = v.x;
            Ash[k0 + 1][m] = v.y;
            Ash[k0 + 2][m] = v.z;
            Ash[k0 + 3][m] = v.w;
        }
        #pragma unroll
        for (int j = 0; j < 8; j++) {
            int idx = tid + j * 384;
            int k = idx / 96, c = idx % 96;
            Wsh[k][c] = W[(kc + k) * 96 + c];
        }
        __syncthreads();
        #pragma unroll
        for (int k = 0; k < 32; k++) {
            float4 al = *(const float4*)&Ash[k][rg * 8];
            float4 ah = *(const float4*)&Ash[k][rg * 8 + 4];
            float4 w  = *(const float4*)&Wsh[k][cg * 4];
            float av[8] = {al.x, al.y, al.z, al.w, ah.x, ah.y, ah.z, ah.w};
            float wv[4] = {w.x, w.y, w.z, w.w};
            #pragma unroll
            for (int i = 0; i < 8; i++)
                #pragma unroll
                for (int j = 0; j < 4; j++)
                    acc[i][j] = fmaf(av[i], wv[j], acc[i][j]);
        }
        __syncthreads();
    }
    int c0 = cg * 4;
    float bv[4];
    #pragma unroll
    for (int j = 0; j < 4; j++) bv[j] = bias[c0 + j];
    int r0 = rowBase + rg * 8;
    #pragma unroll
    for (int i = 0; i < 8; i++) {
        int r = r0 + i;
        if (r < M) {
            float v0 = lrelu01(acc[i][0] + bv[0]);
            float v1 = lrelu01(acc[i][1] + bv[1]);
            float v2 = lrelu01(acc[i][2] + bv[2]);
            float v3 = lrelu01(acc[i][3] + bv[3]);
            *(float4*)&C[r * 96 + c0] = make_float4(v0, v1, v2, v3);
        }
    }
}

// ---------------- K=96 GEMM: W resident + double-buffered A ----------------
#define DSM96 (96 * 96 * 4 + 2 * 32 * 132 * 4)   // 70656
template <int ACT, int MODE, int SCORES>
__global__ __launch_bounds__(384, 2) void gemm96w(
    const float* __restrict__ A, const float* __restrict__ A2,
    const float* __restrict__ gma, const float* __restrict__ bta,
    const float* __restrict__ sumP, const float* __restrict__ sqP,
    const float* __restrict__ W, const float* __restrict__ bias,
    const float* __restrict__ as_, const float* __restrict__ ad_,
    float* __restrict__ ssO, float* __restrict__ sdO,
    void* __restrict__ Cv, int M)
{
    extern __shared__ __align__(16) float dsm[];
    float* Wsh = dsm;                                  // [96*96]
    float (*Ash)[32][132] = (float (*)[32][132])(dsm + 9216);   // [2][32][132]
    float2 (*sSD)[25] = (float2 (*)[25])(dsm + 9216);  // reuses Ash region
    __shared__ float s_sc[96], s_sh[96];
    int tid = threadIdx.x;
    #pragma unroll
    for (int j = 0; j < 24; j++) Wsh[tid + j * 384] = W[tid + j * 384];
    if (MODE == 1) {
        if (tid < 96) {
            float mu = sumP[tid] * (1.f / Nn);
            float var = sqP[tid] * (1.f / Nn) - mu * mu;
            float is = rsqrtf(var + BNEPS);
            float gv = gma[tid];
            s_sc[tid] = gv * is;
            s_sh[tid] = bta[tid] - mu * gv * is;
        }
        __syncthreads();
    }
    int cg = tid % 24;
    int rg = tid / 24;
    int rowBase = blockIdx.x * 128;
    float acc[8][4] = {};
    float4 pf[3];

    auto loadA = [&](int kc) {
        #pragma unroll
        for (int it = 0; it < 3; it++) {
            int idx = tid + it * 384;
            if (idx < 1024) {
                int m = idx >> 3, kq = idx & 7;
                int r = rowBase + m;
                float4 v = make_float4(0.f, 0.f, 0.f, 0.f);
                if (r < M) {
                    v = *(const float4*)&A[r * 96 + kc + kq * 4];
                    if (MODE == 1) {
                        float4 u = *(const float4*)&A2[r * 96 + kc + kq * 4];
                        int c = kc + kq * 4;
                        v.x = lrelu01(fmaf(v.x, s_sc[c + 0], s_sh[c + 0])) + u.x;
                        v.y = lrelu01(fmaf(v.y, s_sc[c + 1], s_sh[c + 1])) + u.y;
                        v.z = lrelu01(fmaf(v.z, s_sc[c + 2], s_sh[c + 2])) + u.z;
                        v.w = lrelu01(fmaf(v.w, s_sc[c + 3], s_sh[c + 3])) + u.w;
                    }
                }
                pf[it] = v;
            }
        }
    };
    auto stsA = [&](int buf) {
        #pragma unroll
        for (int it = 0; it < 3; it++) {
            int idx = tid + it * 384;
            if (idx < 1024) {
                int m = idx >> 3, kq = idx & 7;
                int k0 = kq * 4;
                Ash[buf][k0 + 0][m] = pf[it].x;
                Ash[buf][k0 + 1][m] = pf[it].y;
                Ash[buf][k0 + 2][m] = pf[it].z;
                Ash[buf][k0 + 3][m] = pf[it].w;
            }
        }
    };

    loadA(0);
    stsA(0);
    __syncthreads();
    #pragma unroll
    for (int c = 0; c < 3; c++) {
        if (c < 2) loadA((c + 1) * 32);
        int buf = c & 1;
        const float* wrow = Wsh + c * 32 * 96 + cg * 4;
        #pragma unroll
        for (int k = 0; k < 32; k++) {
            float4 al = *(const float4*)&Ash[buf][k][rg * 8];
            float4 ah = *(const float4*)&Ash[buf][k][rg * 8 + 4];
            float4 w  = *(const float4*)(wrow + k * 96);
            float av[8] = {al.x, al.y, al.z, al.w, ah.x, ah.y, ah.z, ah.w};
            float wv[4] = {w.x, w.y, w.z, w.w};
            #pragma unroll
            for (int i = 0; i < 8; i++)
                #pragma unroll
                for (int j = 0; j < 4; j++)
                    acc[i][j] = fmaf(av[i], wv[j], acc[i][j]);
        }
        if (c < 2) {
            stsA(buf ^ 1);
            __syncthreads();
        }
    }
    __syncthreads();   // Ash dead; safe to alias as sSD

    int c0 = cg * 4;
    float bv[4];
    #pragma unroll
    for (int j = 0; j < 4; j++) bv[j] = bias ? bias[c0 + j] : 0.f;
    float asv[4], adv[4];
    if (SCORES) {
        #pragma unroll
        for (int j = 0; j < 4; j++) { asv[j] = as_[c0 + j]; adv[j] = ad_[c0 + j]; }
    }
    int r0 = rowBase + rg * 8;
    #pragma unroll
    for (int i = 0; i < 8; i++) {
        int r = r0 + i;
        if (SCORES) {
            float s1 = acc[i][0] * asv[0] + acc[i][1] * asv[1] + acc[i][2] * asv[2] + acc[i][3] * asv[3];
            float s2 = acc[i][0] * adv[0] + acc[i][1] * adv[1] + acc[i][2] * adv[2] + acc[i][3] * adv[3];
            sSD[rg * 8 + i][cg] = make_float2(s1, s2);
        }
        if (r < M) {
            float v0 = acc[i][0] + bv[0];
            float v1 = acc[i][1] + bv[1];
            float v2 = acc[i][2] + bv[2];
            float v3 = acc[i][3] + bv[3];
            if (ACT) { v0 = lrelu01(v0); v1 = lrelu01(v1); v2 = lrelu01(v2); v3 = lrelu01(v3); }
            if (SCORES) {
                __half2 h01 = __floats2half2_rn(v0, v1);
                __half2 h23 = __floats2half2_rn(v2, v3);
                uint2 pk = make_uint2(*(unsigned*)&h01, *(unsigned*)&h23);
                *(uint2*)((__half*)Cv + r * 96 + c0) = pk;
            } else {
                *(float4*)((float*)Cv + r * 96 + c0) = make_float4(v0, v1, v2, v3);
            }
        }
    }
    if (SCORES) {
        __syncthreads();
        if (tid < 128) {
            float s1 = 0.f, s2 = 0.f;
            #pragma unroll
            for (int c = 0; c < 24; c++) {
                float2 v = sSD[tid][c];
                s1 += v.x; s2 += v.y;
            }
            int r = rowBase + tid;
            if (r < M) { ssO[r] = s1; sdO[r] = s2; }
        }
    }
}

// ---------------- GAT aggregation: R13-proven structure (scalar half gather) --
__global__ __launch_bounds__(512) void agg_k(
    const __half* __restrict__ hp,
    const float* __restrict__ ss, const float* __restrict__ sd,
    const float* __restrict__ bias, float* __restrict__ out,
    float* __restrict__ sumP, float* __restrict__ sqP)
{
    __shared__ float bw0[16][96];
    __shared__ float bw1[16][96];
    int tid = threadIdx.x;
    int warp = tid >> 5, lane = tid & 31;
    int d = (blockIdx.x * blockDim.x + tid) >> 5;
    float v0 = 0.f, v1 = 0.f, v2 = 0.f;
    if (d < Nn) {
        int j = g_rs[d], s1e = g_rs[d + 1];
        float sdd = sd[d];
        float dA = 0.f, dB = 0.f;
        float a0A = 0.f, a1A = 0.f, a2A = 0.f;
        float a0B = 0.f, a1B = 0.f, a2B = 0.f;
        for (; j + 2 <= s1e; j += 2) {
            int sA = g_csr[j], sB = g_csr[j + 1];
            float eA = ss[sA] + sdd;
            float eB = ss[sB] + sdd;
            eA = (eA >= 0.f) ? eA : 0.2f * eA;
            eB = (eB >= 0.f) ? eB : 0.2f * eB;
            float wA = __expf(eA), wB = __expf(eB);
            const __half* rA = hp + (size_t)sA * 96;
            const __half* rB = hp + (size_t)sB * 96;
            dA += wA;  dB += wB;
            a0A = fmaf(wA, __half2float(rA[lane]), a0A);
            a0B = fmaf(wB, __half2float(rB[lane]), a0B);
            a1A = fmaf(wA, __half2float(rA[lane + 32]), a1A);
            a1B = fmaf(wB, __half2float(rB[lane + 32]), a1B);
            a2A = fmaf(wA, __half2float(rA[lane + 64]), a2A);
            a2B = fmaf(wB, __half2float(rB[lane + 64]), a2B);
        }
        if (j < s1e) {
            int sA = g_csr[j];
            float eA = ss[sA] + sdd;
            eA = (eA >= 0.f) ? eA : 0.2f * eA;
            float wA = __expf(eA);
            const __half* rA = hp + (size_t)sA * 96;
            dA += wA;
            a0A = fmaf(wA, __half2float(rA[lane]), a0A);
            a1A = fmaf(wA, __half2float(rA[lane + 32]), a1A);
            a2A = fmaf(wA, __half2float(rA[lane + 64]), a2A);
        }
        float inv = 1.f / (dA + dB);
        v0 = (a0A + a0B) * inv + bias[lane];
        v1 = (a1A + a1B) * inv + bias[lane + 32];
        v2 = (a2A + a2B) * inv + bias[lane + 64];
        out[d * 96 + lane]      = v0;
        out[d * 96 + lane + 32] = v1;
        out[d * 96 + lane + 64] = v2;
    }
    bw0[warp][lane]      = v0;       bw1[warp][lane]      = v0 * v0;
    bw0[warp][lane + 32] = v1;       bw1[warp][lane + 32] = v1 * v1;
    bw0[warp][lane + 64] = v2;       bw1[warp][lane + 64] = v2 * v2;
    __syncthreads();
    if (tid < 96) {
        float s = 0.f, q = 0.f;
        #pragma unroll
        for (int w = 0; w < 16; w++) { s += bw0[w][tid]; q += bw1[w][tid]; }
        atomicAdd(&sumP[tid], s);
        atomicAdd(&sqP[tid], q);
    }
}

// ---------------- fused BN-apply + Poincare expmap0 + segment pooling ----------------
__global__ void expool_k(const float* __restrict__ t, const float* __restrict__ idn,
                         const float* __restrict__ gma, const float* __restrict__ bta,
                         const float* __restrict__ sumP, const float* __restrict__ sqP,
                         const int* __restrict__ batch)
{
    __shared__ float sp[Gg * Hh];
    __shared__ float scn[Gg];
    __shared__ float s_sc[96], s_sh[96];
    if (threadIdx.x < 96) {
        int c = threadIdx.x;
        float mu = sumP[c] * (1.f / Nn);
        float var = sqP[c] * (1.f / Nn) - mu * mu;
        float is = rsqrtf(var + BNEPS);
        float gv = gma[c];
        s_sc[c] = gv * is;
        s_sh[c] = bta[c] - mu * gv * is;
    }
    for (int i = threadIdx.x; i < Gg * Hh; i += blockDim.x) sp[i] = 0.f;
    if (threadIdx.x < Gg) scn[threadIdx.x] = 0.f;
    __syncthreads();
    int lane = threadIdx.x & 31;
    int warp = (blockIdx.x * blockDim.x + threadIdx.x) >> 5;
    int nwarps = (gridDim.x * blockDim.x) >> 5;
    for (int n = warp; n < Nn; n += nwarps) {
        float v0 = lrelu01(fmaf(t[n * 96 + lane],      s_sc[lane],      s_sh[lane]))      + idn[n * 96 + lane];
        float v1 = lrelu01(fmaf(t[n * 96 + lane + 32], s_sc[lane + 32], s_sh[lane + 32])) + idn[n * 96 + lane + 32];
        float v2 = lrelu01(fmaf(t[n * 96 + lane + 64], s_sc[lane + 64], s_sh[lane + 64])) + idn[n * 96 + lane + 64];
        float q = v0 * v0 + v1 * v1 + v2 * v2;
        #pragma unroll
        for (int o = 16; o; o >>= 1) q += __shfl_xor_sync(0xffffffffu, q, o);
        float nrm = fmaxf(sqrtf(q), 1e-15f);
        float s = tanhf(nrm) / nrm;
        int g = batch[n];
        atomicAdd(&sp[g * 96 + lane], v0 * s);
        atomicAdd(&sp[g * 96 + lane + 32], v1 * s);
        atomicAdd(&sp[g * 96 + lane + 64], v2 * s);
        if (lane == 0) atomicAdd(&scn[g], 1.f);
    }
    __syncthreads();
    for (int i = threadIdx.x; i < Gg * Hh; i += blockDim.x) atomicAdd(&g_pooled[i], sp[i]);
    if (threadIdx.x < Gg) atomicAdd(&g_cnt[threadIdx.x], scn[threadIdx.x]);
}

// ---------------- head ----------------
__global__ void head_k(const float* __restrict__ fc3W, const float* __restrict__ fc3b,
                       const float* __restrict__ fc4W, const float* __restrict__ fc4b,
                       float* __restrict__ out)
{
    __shared__ float p[Gg * Hh];
    __shared__ float o1[Gg * 48];
    for (int i = threadIdx.x; i < Gg * Hh; i += blockDim.x) {
        int g = i / 96;
        p[i] = g_pooled[i] / fmaxf(g_cnt[g], 1.f);
    }
    __syncthreads();
    for (int i = threadIdx.x; i < Gg * 48; i += blockDim.x) {
        int g = i / 48, c = i % 48;
        float a = fc3b[c];
        for (int k = 0; k < 96; k++) a = fmaf(p[g * 96 + k], fc3W[k * 48 + c], a);
        o1[i] = lrelu01(a);
    }
    __syncthreads();
    for (int i = threadIdx.x; i < Gg * NCLS; i += blockDim.x) {
        int g = i / NCLS, c = i % NCLS;
        float a = fc4b[c];
        for (int k = 0; k < 48; k++) a = fmaf(o1[g * 48 + k], fc4W[k * NCLS + c], a);
        out[i] = a;
    }
}

// ---------------- launch ----------------
extern "C" void kernel_launch(void* const* d_in, const int* in_sizes, int n_in,
                              void* d_out, int out_size)
{
    const float* x     = (const float*)d_in[0];
    const int*   ei    = (const int*)d_in[1];
    const int*   batch = (const int*)d_in[2];
    const float* embW  = (const float*)d_in[3];
    const float* embB  = (const float*)d_in[4];
    const float* cW[3]  = {(const float*)d_in[5],  (const float*)d_in[9],  (const float*)d_in[13]};
    const float* cAS[3] = {(const float*)d_in[6],  (const float*)d_in[10], (const float*)d_in[14]};
    const float* cAD[3] = {(const float*)d_in[7],  (const float*)d_in[11], (const float*)d_in[15]};
    const float* cB[3]  = {(const float*)d_in[8],  (const float*)d_in[12], (const float*)d_in[16]};
    const float* fcW[2] = {(const float*)d_in[17], (const float*)d_in[19]};
    const float* fcB[2] = {(const float*)d_in[18], (const float*)d_in[20]};
    const float* bnG[3] = {(const float*)d_in[21], (const float*)d_in[23], (const float*)d_in[25]};
    const float* bnB[3] = {(const float*)d_in[22], (const float*)d_in[24], (const float*)d_in[26]};
    const float* fc3W = (const float*)d_in[27];
    const float* fc3b = (const float*)d_in[28];
    const float* fc4W = (const float*)d_in[29];
    const float* fc4b = (const float*)d_in[30];
    float* out = (float*)d_out;

    float *ph, *pid, *ptmp, *pss, *psd, *pbs, *pbq;
    __half* phph;
    cudaGetSymbolAddress((void**)&ph,   g_h);
    cudaGetSymbolAddress((void**)&pid,  g_id);
    cudaGetSymbolAddress((void**)&phph, g_hph);
    cudaGetSymbolAddress((void**)&ptmp, g_tmp);
    cudaGetSymbolAddress((void**)&pss,  g_ss);
    cudaGetSymbolAddress((void**)&psd,  g_sd);
    cudaGetSymbolAddress((void**)&pbs,  g_bnsum);
    cudaGetSymbolAddress((void**)&pbq,  g_bnsq);

    const int EB = (ETOT + 255) / 256;
    const int GB = (Nn + 127) / 128;
    const int AB = (Nn * 32 + 511) / 512;

    cudaFuncSetAttribute(gemm96w<0, 0, 1>, cudaFuncAttributeMaxDynamicSharedMemorySize, DSM96);
    cudaFuncSetAttribute(gemm96w<1, 1, 0>, cudaFuncAttributeMaxDynamicSharedMemorySize, DSM96);

    // Fork: CSR build concurrent with embed GEMM. Streams/events intentionally
    // leaked (destroying them mid-capture would abort graph capture).
    cudaStream_t s1;
    cudaStreamCreateWithFlags(&s1, cudaStreamNonBlocking);
    cudaEvent_t evFork, evJoin;
    cudaEventCreateWithFlags(&evFork, cudaEventDisableTiming);
    cudaEventCreateWithFlags(&evJoin, cudaEventDisableTiming);

    cudaEventRecord(evFork, 0);
    cudaStreamWaitEvent(s1, evFork, 0);
    zero_k<<<256, 256, 0, s1>>>();
    count_k<<<EB, 256, 0, s1>>>(ei);
    scan_k<<<1, 1024, 0, s1>>>();
    scatter_k<<<EB, 256, 0, s1>>>(ei);
    cudaEventRecord(evJoin, s1);

    // embed: id = lrelu(x @ embW + embB)   (single output buffer; h first
    // written by the layer-0 fc GEMM, layer-0 conv reads id directly)
    gemm128_emb<<<GB, 384>>>(x, embW, embB, pid, Nn, 256);

    for (int l = 0; l < 3; l++) {
        const float* hin = (l == 0) ? pid : ph;
        // hp(fp16) = hin @ cW  (+ fused atomic-free attention scores)
        gemm96w<0, 0, 1><<<GB, 384, DSM96>>>(hin, nullptr, nullptr, nullptr, nullptr, nullptr,
                                             cW[l], nullptr, cAS[l], cAD[l], pss, psd,
                                             (void*)phph, Nn);
        if (l == 0) cudaStreamWaitEvent(0, evJoin, 0);   // CSR + zeroed BN slots ready
        agg_k<<<AB, 512>>>(phph, pss, psd, cB[l], ptmp, pbs + l * Hh, pbq + l * Hh);
        if (l < 2) {
            // h = lrelu( (lrelu(bn(tmp)) + id) @ fcW + fcB ) — BN fused into A-load
            gemm96w<1, 1, 0><<<GB, 384, DSM96>>>(ptmp, pid, bnG[l], bnB[l], pbs + l * Hh, pbq + l * Hh,
                                                 fcW[l], fcB[l], nullptr, nullptr, nullptr, nullptr,
                                                 (void*)ph, Nn);
        }
    }

    expool_k<<<160, 256>>>(ptmp, pid, bnG[2], bnB[2], pbs + 2 * Hh, pbq + 2 * Hh, batch);
    head_k<<<1, 256>>>(fc3W, fc3b, fc4W, fc4b, out);
}